// round 8
// baseline (speedup 1.0000x reference)
#include <cuda_runtime.h>
#include <cuda_fp16.h>
#include <cstdint>

#define NF 128          // node feature dim F
#define EFD 7           // edge feature dim
#define NMAX 100000     // node count

// Scratch for h = nfeat @ W.T + b, stored fp16 (25.6 MB)
__device__ __half g_h[(size_t)NMAX * NF];

// ---------------------------------------------------------------------------
// Kernel A: h = nfeat @ W.T + b (fp32 accum, fp16 store);
//           out = relu(h_fp32 + root_emb) / degs  (full precision)
// Scalar-FFMA tiled SGEMM, 128x128 tile, BK=16, 256 threads, 8x8/thread.
// ---------------------------------------------------------------------------
#define BM 128
#define BK 16

__global__ void __launch_bounds__(256)
gemm_h_kernel(const float* __restrict__ A,      // nfeat [N,128]
              const float* __restrict__ W,      // [128,128]
              const float* __restrict__ bvec,   // [128]
              const float* __restrict__ root,   // [1,128]
              const float* __restrict__ degs,   // [N]
              __half* __restrict__ hout,        // [N,128] fp16
              float* __restrict__ out,          // [N,128]
              int N)
{
    __shared__ float sA[BK][BM];      // [k][m]
    __shared__ float sW[BK][NF];      // [k][j] = W[j][kc+k]

    const int tid = threadIdx.x;
    const int tx  = tid & 15;
    const int ty  = tid >> 4;
    const int m0  = blockIdx.x * BM;

    float acc[8][8];
#pragma unroll
    for (int i = 0; i < 8; i++)
#pragma unroll
        for (int j = 0; j < 8; j++) acc[i][j] = 0.f;

    float bj[8], rj[8];
#pragma unroll
    for (int j = 0; j < 8; j++) {
        bj[j] = __ldg(bvec + tx * 8 + j);
        rj[j] = __ldg(root + tx * 8 + j);
    }

    for (int kc = 0; kc < NF; kc += BK) {
#pragma unroll
        for (int i = 0; i < 2; i++) {
            int r = (tid >> 2) + i * 64;
            int c = (tid & 3) * 4;
            float4 v = make_float4(0.f, 0.f, 0.f, 0.f);
            int gr = m0 + r;
            if (gr < N)
                v = *reinterpret_cast<const float4*>(A + (size_t)gr * NF + kc + c);
            sA[c + 0][r] = v.x; sA[c + 1][r] = v.y;
            sA[c + 2][r] = v.z; sA[c + 3][r] = v.w;
        }
#pragma unroll
        for (int i = 0; i < 2; i++) {
            int j = (tid >> 2) + i * 64;
            int c = (tid & 3) * 4;
            float4 v = *reinterpret_cast<const float4*>(W + (size_t)j * NF + kc + c);
            sW[c + 0][j] = v.x; sW[c + 1][j] = v.y;
            sW[c + 2][j] = v.z; sW[c + 3][j] = v.w;
        }
        __syncthreads();

#pragma unroll
        for (int k = 0; k < BK; k++) {
            float a[8], w[8];
#pragma unroll
            for (int i = 0; i < 8; i += 4) {
                *reinterpret_cast<float4*>(&a[i]) =
                    *reinterpret_cast<const float4*>(&sA[k][ty * 8 + i]);
                *reinterpret_cast<float4*>(&w[i]) =
                    *reinterpret_cast<const float4*>(&sW[k][tx * 8 + i]);
            }
#pragma unroll
            for (int i = 0; i < 8; i++)
#pragma unroll
                for (int j = 0; j < 8; j++)
                    acc[i][j] = fmaf(a[i], w[j], acc[i][j]);
        }
        __syncthreads();
    }

#pragma unroll
    for (int i = 0; i < 8; i++) {
        int m = m0 + ty * 8 + i;
        if (m < N) {
            float invd = 1.0f / degs[m];
#pragma unroll
            for (int j4 = 0; j4 < 8; j4 += 4) {
                int j = tx * 8 + j4;
                float h0 = acc[i][j4 + 0] + bj[j4 + 0];
                float h1 = acc[i][j4 + 1] + bj[j4 + 1];
                float h2 = acc[i][j4 + 2] + bj[j4 + 2];
                float h3 = acc[i][j4 + 3] + bj[j4 + 3];
                float4 ov;
                ov.x = fmaxf(h0 + rj[j4 + 0], 0.f) * invd;
                ov.y = fmaxf(h1 + rj[j4 + 1], 0.f) * invd;
                ov.z = fmaxf(h2 + rj[j4 + 2], 0.f) * invd;
                ov.w = fmaxf(h3 + rj[j4 + 3], 0.f) * invd;
                // fp16 h store (8B)
                __half2 p0 = __floats2half2_rn(h0, h1);
                __half2 p1 = __floats2half2_rn(h2, h3);
                uint2 hst;
                hst.x = *reinterpret_cast<uint32_t*>(&p0);
                hst.y = *reinterpret_cast<uint32_t*>(&p1);
                *reinterpret_cast<uint2*>(hout + (size_t)m * NF + j) = hst;
                *reinterpret_cast<float4*>(out + (size_t)m * NF + j) = ov;
            }
        }
    }
}

// ---------------------------------------------------------------------------
// Kernel B: 8 edges per warp per iteration, h gathered as fp16 (8B/lane).
// All 8 gathers in flight before any consume; efeat register-resident
// (14 uniform LDG.128); red.global.add.v4.f32 scatter.
// ---------------------------------------------------------------------------
__global__ void __launch_bounds__(256)
edge_kernel(const float* __restrict__ efeat,   // [E,7]
            const float* __restrict__ norm,    // [E]
            const int*   __restrict__ src,
            const int*   __restrict__ dst,
            const float* __restrict__ We,      // [128,7]
            const float* __restrict__ be,      // [128]
            const __half* __restrict__ h,      // [N,128] fp16
            float* __restrict__ out,           // [N,128]
            int E)
{
    const int lane = threadIdx.x & 31;
    const int j0   = lane * 4;

    float w[4][EFD], bias[4];
#pragma unroll
    for (int j = 0; j < 4; j++) {
        bias[j] = __ldg(be + j0 + j);
#pragma unroll
        for (int k = 0; k < EFD; k++)
            w[j][k] = __ldg(We + (size_t)(j0 + j) * EFD + k);
    }

    const int warp_id = (blockIdx.x * blockDim.x + threadIdx.x) >> 5;
    const int nwarps  = (gridDim.x * blockDim.x) >> 5;
    const int Emain   = E & ~7;

    for (int e0 = warp_id * 8; e0 < Emain; e0 += nwarps * 8) {
        const int4   sa  = __ldcs(reinterpret_cast<const int4*>(src + e0));
        const int4   sb4 = __ldcs(reinterpret_cast<const int4*>(src + e0 + 4));
        const int4   da  = __ldcs(reinterpret_cast<const int4*>(dst + e0));
        const int4   db  = __ldcs(reinterpret_cast<const int4*>(dst + e0 + 4));
        const float4 na  = __ldcs(reinterpret_cast<const float4*>(norm + e0));
        const float4 nb  = __ldcs(reinterpret_cast<const float4*>(norm + e0 + 4));

        const int s[8] = {sa.x, sa.y, sa.z, sa.w, sb4.x, sb4.y, sb4.z, sb4.w};
        const int d[8] = {da.x, da.y, da.z, da.w, db.x, db.y, db.z, db.w};
        const float nr[8] = {na.x, na.y, na.z, na.w, nb.x, nb.y, nb.z, nb.w};

        // all 8 fp16 gathers in flight before any consume (uint2 = 4 halves)
        uint2 hvr[8];
#pragma unroll
        for (int u = 0; u < 8; u++)
            hvr[u] = *reinterpret_cast<const uint2*>(h + (size_t)s[u] * NF + j0);

        // efeat: 8 edges x 7 feats = 56 floats = 14 aligned float4 (streaming)
        float ef[56];
#pragma unroll
        for (int q = 0; q < 14; q++)
            *reinterpret_cast<float4*>(&ef[q * 4]) =
                __ldcs(reinterpret_cast<const float4*>(efeat + (size_t)e0 * EFD + q * 4));

#pragma unroll
        for (int u = 0; u < 8; u++) {
            float v0 = bias[0], v1 = bias[1], v2 = bias[2], v3 = bias[3];
#pragma unroll
            for (int k = 0; k < EFD; k++) {
                float x = ef[u * EFD + k];
                v0 = fmaf(w[0][k], x, v0);
                v1 = fmaf(w[1][k], x, v1);
                v2 = fmaf(w[2][k], x, v2);
                v3 = fmaf(w[3][k], x, v3);
            }
            __half2 p0 = *reinterpret_cast<__half2*>(&hvr[u].x);
            __half2 p1 = *reinterpret_cast<__half2*>(&hvr[u].y);
            float2 f01 = __half22float2(p0);
            float2 f23 = __half22float2(p1);

            v0 = fmaxf(f01.x + v0, 0.f) * nr[u];
            v1 = fmaxf(f01.y + v1, 0.f) * nr[u];
            v2 = fmaxf(f23.x + v2, 0.f) * nr[u];
            v3 = fmaxf(f23.y + v3, 0.f) * nr[u];

            float* p = out + (size_t)d[u] * NF + j0;
            asm volatile("red.global.add.v4.f32 [%0], {%1, %2, %3, %4};"
                         :: "l"(p), "f"(v0), "f"(v1), "f"(v2), "f"(v3)
                         : "memory");
        }
    }

    // tail — warp 0
    if (warp_id == 0) {
        for (int e = Emain; e < E; e++) {
            const int   se = __ldg(src + e);
            const int   de = __ldg(dst + e);
            const float nre = __ldg(norm + e);
            float efs[EFD];
#pragma unroll
            for (int k = 0; k < EFD; k++)
                efs[k] = __ldg(efeat + (size_t)e * EFD + k);
            uint2 hraw = *reinterpret_cast<const uint2*>(h + (size_t)se * NF + j0);
            __half2 p0 = *reinterpret_cast<__half2*>(&hraw.x);
            __half2 p1 = *reinterpret_cast<__half2*>(&hraw.y);
            float2 f01 = __half22float2(p0);
            float2 f23 = __half22float2(p1);
            float v0 = bias[0], v1 = bias[1], v2 = bias[2], v3 = bias[3];
#pragma unroll
            for (int k = 0; k < EFD; k++) {
                v0 = fmaf(w[0][k], efs[k], v0);
                v1 = fmaf(w[1][k], efs[k], v1);
                v2 = fmaf(w[2][k], efs[k], v2);
                v3 = fmaf(w[3][k], efs[k], v3);
            }
            v0 = fmaxf(f01.x + v0, 0.f) * nre;
            v1 = fmaxf(f01.y + v1, 0.f) * nre;
            v2 = fmaxf(f23.x + v2, 0.f) * nre;
            v3 = fmaxf(f23.y + v3, 0.f) * nre;
            float* p = out + (size_t)de * NF + j0;
            asm volatile("red.global.add.v4.f32 [%0], {%1, %2, %3, %4};"
                         :: "l"(p), "f"(v0), "f"(v1), "f"(v2), "f"(v3)
                         : "memory");
        }
    }
}

// ---------------------------------------------------------------------------
// Launch.  Input order: nfeat, efeat, degs, norm, src, dst, W, b, We, be, root
// ---------------------------------------------------------------------------
extern "C" void kernel_launch(void* const* d_in, const int* in_sizes, int n_in,
                              void* d_out, int out_size)
{
    const float* nfeat = (const float*)d_in[0];
    const float* efeat = (const float*)d_in[1];
    const float* degs  = (const float*)d_in[2];
    const float* norm  = (const float*)d_in[3];
    const int*   src   = (const int*)  d_in[4];
    const int*   dst   = (const int*)  d_in[5];
    const float* W     = (const float*)d_in[6];
    const float* b     = (const float*)d_in[7];
    const float* We    = (const float*)d_in[8];
    const float* be    = (const float*)d_in[9];
    const float* root  = (const float*)d_in[10];
    float* out = (float*)d_out;

    const int N = in_sizes[0] / NF;
    const int E = in_sizes[4];

    __half* h;
    cudaGetSymbolAddress((void**)&h, g_h);

    int gridA = (N + BM - 1) / BM;
    gemm_h_kernel<<<gridA, 256>>>(nfeat, W, b, root, degs, h, out, N);

    int gridB = 1480;
    edge_kernel<<<gridB, 256>>>(efeat, norm, src, dst, We, be, h, out, E);
}

// round 9
// speedup vs baseline: 1.2162x; 1.2162x over previous
#include <cuda_runtime.h>
#include <cuda_fp16.h>
#include <cstdint>

#define NF 128          // node feature dim F
#define EFD 7           // edge feature dim
#define NMAX 100000     // node count

// Scratch for h = nfeat @ W.T + b, stored fp16 (25.6 MB)
__device__ __half g_h[(size_t)NMAX * NF];

// ---------------------------------------------------------------------------
// Kernel A: h = nfeat @ W.T + b (fp32 accum, fp16 store);
//           out = relu(h_fp32 + root_emb) / degs  (full precision)
// Scalar-FFMA tiled SGEMM, 128x128 tile, BK=16, 256 threads, 8x8/thread.
// ---------------------------------------------------------------------------
#define BM 128
#define BK 16

__global__ void __launch_bounds__(256)
gemm_h_kernel(const float* __restrict__ A,      // nfeat [N,128]
              const float* __restrict__ W,      // [128,128]
              const float* __restrict__ bvec,   // [128]
              const float* __restrict__ root,   // [1,128]
              const float* __restrict__ degs,   // [N]
              __half* __restrict__ hout,        // [N,128] fp16
              float* __restrict__ out,          // [N,128]
              int N)
{
    __shared__ float sA[BK][BM];      // [k][m]
    __shared__ float sW[BK][NF];      // [k][j] = W[j][kc+k]

    const int tid = threadIdx.x;
    const int tx  = tid & 15;
    const int ty  = tid >> 4;
    const int m0  = blockIdx.x * BM;

    float acc[8][8];
#pragma unroll
    for (int i = 0; i < 8; i++)
#pragma unroll
        for (int j = 0; j < 8; j++) acc[i][j] = 0.f;

    float bj[8], rj[8];
#pragma unroll
    for (int j = 0; j < 8; j++) {
        bj[j] = __ldg(bvec + tx * 8 + j);
        rj[j] = __ldg(root + tx * 8 + j);
    }

    for (int kc = 0; kc < NF; kc += BK) {
#pragma unroll
        for (int i = 0; i < 2; i++) {
            int r = (tid >> 2) + i * 64;
            int c = (tid & 3) * 4;
            float4 v = make_float4(0.f, 0.f, 0.f, 0.f);
            int gr = m0 + r;
            if (gr < N)
                v = *reinterpret_cast<const float4*>(A + (size_t)gr * NF + kc + c);
            sA[c + 0][r] = v.x; sA[c + 1][r] = v.y;
            sA[c + 2][r] = v.z; sA[c + 3][r] = v.w;
        }
#pragma unroll
        for (int i = 0; i < 2; i++) {
            int j = (tid >> 2) + i * 64;
            int c = (tid & 3) * 4;
            float4 v = *reinterpret_cast<const float4*>(W + (size_t)j * NF + kc + c);
            sW[c + 0][j] = v.x; sW[c + 1][j] = v.y;
            sW[c + 2][j] = v.z; sW[c + 3][j] = v.w;
        }
        __syncthreads();

#pragma unroll
        for (int k = 0; k < BK; k++) {
            float a[8], w[8];
#pragma unroll
            for (int i = 0; i < 8; i += 4) {
                *reinterpret_cast<float4*>(&a[i]) =
                    *reinterpret_cast<const float4*>(&sA[k][ty * 8 + i]);
                *reinterpret_cast<float4*>(&w[i]) =
                    *reinterpret_cast<const float4*>(&sW[k][tx * 8 + i]);
            }
#pragma unroll
            for (int i = 0; i < 8; i++)
#pragma unroll
                for (int j = 0; j < 8; j++)
                    acc[i][j] = fmaf(a[i], w[j], acc[i][j]);
        }
        __syncthreads();
    }

#pragma unroll
    for (int i = 0; i < 8; i++) {
        int m = m0 + ty * 8 + i;
        if (m < N) {
            float invd = 1.0f / degs[m];
#pragma unroll
            for (int j4 = 0; j4 < 8; j4 += 4) {
                int j = tx * 8 + j4;
                float h0 = acc[i][j4 + 0] + bj[j4 + 0];
                float h1 = acc[i][j4 + 1] + bj[j4 + 1];
                float h2 = acc[i][j4 + 2] + bj[j4 + 2];
                float h3 = acc[i][j4 + 3] + bj[j4 + 3];
                float4 ov;
                ov.x = fmaxf(h0 + rj[j4 + 0], 0.f) * invd;
                ov.y = fmaxf(h1 + rj[j4 + 1], 0.f) * invd;
                ov.z = fmaxf(h2 + rj[j4 + 2], 0.f) * invd;
                ov.w = fmaxf(h3 + rj[j4 + 3], 0.f) * invd;
                __half2 p0 = __floats2half2_rn(h0, h1);
                __half2 p1 = __floats2half2_rn(h2, h3);
                uint2 hst;
                hst.x = *reinterpret_cast<uint32_t*>(&p0);
                hst.y = *reinterpret_cast<uint32_t*>(&p1);
                *reinterpret_cast<uint2*>(hout + (size_t)m * NF + j) = hst;
                *reinterpret_cast<float4*>(out + (size_t)m * NF + j) = ov;
            }
        }
    }
}

// ---------------------------------------------------------------------------
// Kernel B: 8 edges per warp per iteration, h gathered as fp16 (8B/lane).
// __launch_bounds__(256, 2) caps regs at 128 -> 2 CTAs/SM (16 warps).
// ---------------------------------------------------------------------------
__global__ void __launch_bounds__(256, 2)
edge_kernel(const float* __restrict__ efeat,   // [E,7]
            const float* __restrict__ norm,    // [E]
            const int*   __restrict__ src,
            const int*   __restrict__ dst,
            const float* __restrict__ We,      // [128,7]
            const float* __restrict__ be,      // [128]
            const __half* __restrict__ h,      // [N,128] fp16
            float* __restrict__ out,           // [N,128]
            int E)
{
    const int lane = threadIdx.x & 31;
    const int j0   = lane * 4;

    float w[4][EFD], bias[4];
#pragma unroll
    for (int j = 0; j < 4; j++) {
        bias[j] = __ldg(be + j0 + j);
#pragma unroll
        for (int k = 0; k < EFD; k++)
            w[j][k] = __ldg(We + (size_t)(j0 + j) * EFD + k);
    }

    const int warp_id = (blockIdx.x * blockDim.x + threadIdx.x) >> 5;
    const int nwarps  = (gridDim.x * blockDim.x) >> 5;
    const int Emain   = E & ~7;

    for (int e0 = warp_id * 8; e0 < Emain; e0 += nwarps * 8) {
        const int4   sa  = __ldcs(reinterpret_cast<const int4*>(src + e0));
        const int4   sb4 = __ldcs(reinterpret_cast<const int4*>(src + e0 + 4));
        const int4   da  = __ldcs(reinterpret_cast<const int4*>(dst + e0));
        const int4   db  = __ldcs(reinterpret_cast<const int4*>(dst + e0 + 4));
        const float4 na  = __ldcs(reinterpret_cast<const float4*>(norm + e0));
        const float4 nb  = __ldcs(reinterpret_cast<const float4*>(norm + e0 + 4));

        const int s[8] = {sa.x, sa.y, sa.z, sa.w, sb4.x, sb4.y, sb4.z, sb4.w};
        const int d[8] = {da.x, da.y, da.z, da.w, db.x, db.y, db.z, db.w};
        const float nr[8] = {na.x, na.y, na.z, na.w, nb.x, nb.y, nb.z, nb.w};

        // all 8 fp16 gathers in flight before any consume (uint2 = 4 halves)
        uint2 hvr[8];
#pragma unroll
        for (int u = 0; u < 8; u++)
            hvr[u] = *reinterpret_cast<const uint2*>(h + (size_t)s[u] * NF + j0);

        // efeat: 8 edges x 7 feats = 56 floats = 14 aligned float4 (streaming)
        float ef[56];
#pragma unroll
        for (int q = 0; q < 14; q++)
            *reinterpret_cast<float4*>(&ef[q * 4]) =
                __ldcs(reinterpret_cast<const float4*>(efeat + (size_t)e0 * EFD + q * 4));

#pragma unroll
        for (int u = 0; u < 8; u++) {
            float v0 = bias[0], v1 = bias[1], v2 = bias[2], v3 = bias[3];
#pragma unroll
            for (int k = 0; k < EFD; k++) {
                float x = ef[u * EFD + k];
                v0 = fmaf(w[0][k], x, v0);
                v1 = fmaf(w[1][k], x, v1);
                v2 = fmaf(w[2][k], x, v2);
                v3 = fmaf(w[3][k], x, v3);
            }
            __half2 p0 = *reinterpret_cast<__half2*>(&hvr[u].x);
            __half2 p1 = *reinterpret_cast<__half2*>(&hvr[u].y);
            float2 f01 = __half22float2(p0);
            float2 f23 = __half22float2(p1);

            v0 = fmaxf(f01.x + v0, 0.f) * nr[u];
            v1 = fmaxf(f01.y + v1, 0.f) * nr[u];
            v2 = fmaxf(f23.x + v2, 0.f) * nr[u];
            v3 = fmaxf(f23.y + v3, 0.f) * nr[u];

            float* p = out + (size_t)d[u] * NF + j0;
            asm volatile("red.global.add.v4.f32 [%0], {%1, %2, %3, %4};"
                         :: "l"(p), "f"(v0), "f"(v1), "f"(v2), "f"(v3)
                         : "memory");
        }
    }

    // tail — warp 0
    if (warp_id == 0) {
        for (int e = Emain; e < E; e++) {
            const int   se = __ldg(src + e);
            const int   de = __ldg(dst + e);
            const float nre = __ldg(norm + e);
            float efs[EFD];
#pragma unroll
            for (int k = 0; k < EFD; k++)
                efs[k] = __ldg(efeat + (size_t)e * EFD + k);
            uint2 hraw = *reinterpret_cast<const uint2*>(h + (size_t)se * NF + j0);
            __half2 p0 = *reinterpret_cast<__half2*>(&hraw.x);
            __half2 p1 = *reinterpret_cast<__half2*>(&hraw.y);
            float2 f01 = __half22float2(p0);
            float2 f23 = __half22float2(p1);
            float v0 = bias[0], v1 = bias[1], v2 = bias[2], v3 = bias[3];
#pragma unroll
            for (int k = 0; k < EFD; k++) {
                v0 = fmaf(w[0][k], efs[k], v0);
                v1 = fmaf(w[1][k], efs[k], v1);
                v2 = fmaf(w[2][k], efs[k], v2);
                v3 = fmaf(w[3][k], efs[k], v3);
            }
            v0 = fmaxf(f01.x + v0, 0.f) * nre;
            v1 = fmaxf(f01.y + v1, 0.f) * nre;
            v2 = fmaxf(f23.x + v2, 0.f) * nre;
            v3 = fmaxf(f23.y + v3, 0.f) * nre;
            float* p = out + (size_t)de * NF + j0;
            asm volatile("red.global.add.v4.f32 [%0], {%1, %2, %3, %4};"
                         :: "l"(p), "f"(v0), "f"(v1), "f"(v2), "f"(v3)
                         : "memory");
        }
    }
}

// ---------------------------------------------------------------------------
// Launch.  Input order: nfeat, efeat, degs, norm, src, dst, W, b, We, be, root
// ---------------------------------------------------------------------------
extern "C" void kernel_launch(void* const* d_in, const int* in_sizes, int n_in,
                              void* d_out, int out_size)
{
    const float* nfeat = (const float*)d_in[0];
    const float* efeat = (const float*)d_in[1];
    const float* degs  = (const float*)d_in[2];
    const float* norm  = (const float*)d_in[3];
    const int*   src   = (const int*)  d_in[4];
    const int*   dst   = (const int*)  d_in[5];
    const float* W     = (const float*)d_in[6];
    const float* b     = (const float*)d_in[7];
    const float* We    = (const float*)d_in[8];
    const float* be    = (const float*)d_in[9];
    const float* root  = (const float*)d_in[10];
    float* out = (float*)d_out;

    const int N = in_sizes[0] / NF;
    const int E = in_sizes[4];

    __half* h;
    cudaGetSymbolAddress((void**)&h, g_h);

    int gridA = (N + BM - 1) / BM;
    gemm_h_kernel<<<gridA, 256>>>(nfeat, W, b, root, degs, h, out, N);

    int gridB = 1480;
    edge_kernel<<<gridB, 256>>>(efeat, norm, src, dst, We, be, h, out, E);
}

// round 10
// speedup vs baseline: 1.2518x; 1.0293x over previous
#include <cuda_runtime.h>
#include <cuda_fp16.h>
#include <cstdint>

#define NF 128          // node feature dim F
#define EFD 7           // edge feature dim
#define NMAX 100000     // node count

// Scratch for h = nfeat @ W.T + b, stored fp16 (25.6 MB)
__device__ __half g_h[(size_t)NMAX * NF];

// ---------------------------------------------------------------------------
// Kernel A: h = nfeat @ W.T + b (fp32 accum, fp16 store);
//           out = relu(h_fp32 + root_emb) / degs  (full precision)
// ---------------------------------------------------------------------------
#define BM 128
#define BK 16

__global__ void __launch_bounds__(256)
gemm_h_kernel(const float* __restrict__ A,      // nfeat [N,128]
              const float* __restrict__ W,      // [128,128]
              const float* __restrict__ bvec,   // [128]
              const float* __restrict__ root,   // [1,128]
              const float* __restrict__ degs,   // [N]
              __half* __restrict__ hout,        // [N,128] fp16
              float* __restrict__ out,          // [N,128]
              int N)
{
    __shared__ float sA[BK][BM];
    __shared__ float sW[BK][NF];

    const int tid = threadIdx.x;
    const int tx  = tid & 15;
    const int ty  = tid >> 4;
    const int m0  = blockIdx.x * BM;

    float acc[8][8];
#pragma unroll
    for (int i = 0; i < 8; i++)
#pragma unroll
        for (int j = 0; j < 8; j++) acc[i][j] = 0.f;

    float bj[8], rj[8];
#pragma unroll
    for (int j = 0; j < 8; j++) {
        bj[j] = __ldg(bvec + tx * 8 + j);
        rj[j] = __ldg(root + tx * 8 + j);
    }

    for (int kc = 0; kc < NF; kc += BK) {
#pragma unroll
        for (int i = 0; i < 2; i++) {
            int r = (tid >> 2) + i * 64;
            int c = (tid & 3) * 4;
            float4 v = make_float4(0.f, 0.f, 0.f, 0.f);
            int gr = m0 + r;
            if (gr < N)
                v = *reinterpret_cast<const float4*>(A + (size_t)gr * NF + kc + c);
            sA[c + 0][r] = v.x; sA[c + 1][r] = v.y;
            sA[c + 2][r] = v.z; sA[c + 3][r] = v.w;
        }
#pragma unroll
        for (int i = 0; i < 2; i++) {
            int j = (tid >> 2) + i * 64;
            int c = (tid & 3) * 4;
            float4 v = *reinterpret_cast<const float4*>(W + (size_t)j * NF + kc + c);
            sW[c + 0][j] = v.x; sW[c + 1][j] = v.y;
            sW[c + 2][j] = v.z; sW[c + 3][j] = v.w;
        }
        __syncthreads();

#pragma unroll
        for (int k = 0; k < BK; k++) {
            float a[8], w[8];
#pragma unroll
            for (int i = 0; i < 8; i += 4) {
                *reinterpret_cast<float4*>(&a[i]) =
                    *reinterpret_cast<const float4*>(&sA[k][ty * 8 + i]);
                *reinterpret_cast<float4*>(&w[i]) =
                    *reinterpret_cast<const float4*>(&sW[k][tx * 8 + i]);
            }
#pragma unroll
            for (int i = 0; i < 8; i++)
#pragma unroll
                for (int j = 0; j < 8; j++)
                    acc[i][j] = fmaf(a[i], w[j], acc[i][j]);
        }
        __syncthreads();
    }

#pragma unroll
    for (int i = 0; i < 8; i++) {
        int m = m0 + ty * 8 + i;
        if (m < N) {
            float invd = 1.0f / degs[m];
#pragma unroll
            for (int j4 = 0; j4 < 8; j4 += 4) {
                int j = tx * 8 + j4;
                float h0 = acc[i][j4 + 0] + bj[j4 + 0];
                float h1 = acc[i][j4 + 1] + bj[j4 + 1];
                float h2 = acc[i][j4 + 2] + bj[j4 + 2];
                float h3 = acc[i][j4 + 3] + bj[j4 + 3];
                float4 ov;
                ov.x = fmaxf(h0 + rj[j4 + 0], 0.f) * invd;
                ov.y = fmaxf(h1 + rj[j4 + 1], 0.f) * invd;
                ov.z = fmaxf(h2 + rj[j4 + 2], 0.f) * invd;
                ov.w = fmaxf(h3 + rj[j4 + 3], 0.f) * invd;
                __half2 p0 = __floats2half2_rn(h0, h1);
                __half2 p1 = __floats2half2_rn(h2, h3);
                uint2 hst;
                hst.x = *reinterpret_cast<uint32_t*>(&p0);
                hst.y = *reinterpret_cast<uint32_t*>(&p1);
                *reinterpret_cast<uint2*>(hout + (size_t)m * NF + j) = hst;
                *reinterpret_cast<float4*>(out + (size_t)m * NF + j) = ov;
            }
        }
    }
}

// ---------------------------------------------------------------------------
// Kernel B: 8 edges/warp/iter, fp16 gathers, next-iter src prefetch,
// efeat in two 28-float chunks (register pressure < 128, no spills).
// ---------------------------------------------------------------------------
__global__ void __launch_bounds__(256, 2)
edge_kernel(const float* __restrict__ efeat,   // [E,7]
            const float* __restrict__ norm,    // [E]
            const int*   __restrict__ src,
            const int*   __restrict__ dst,
            const float* __restrict__ We,      // [128,7]
            const float* __restrict__ be,      // [128]
            const __half* __restrict__ h,      // [N,128] fp16
            float* __restrict__ out,           // [N,128]
            int E)
{
    const int lane = threadIdx.x & 31;
    const int j0   = lane * 4;

    float w[4][EFD], bias[4];
#pragma unroll
    for (int j = 0; j < 4; j++) {
        bias[j] = __ldg(be + j0 + j);
#pragma unroll
        for (int k = 0; k < EFD; k++)
            w[j][k] = __ldg(We + (size_t)(j0 + j) * EFD + k);
    }

    const int warp_id = (blockIdx.x * blockDim.x + threadIdx.x) >> 5;
    const int nwarps  = (gridDim.x * blockDim.x) >> 5;
    const int Emain   = E & ~7;
    const int estep   = nwarps * 8;

    int e0 = warp_id * 8;
    int4 sa, sb;
    if (e0 < Emain) {
        sa = __ldcs(reinterpret_cast<const int4*>(src + e0));
        sb = __ldcs(reinterpret_cast<const int4*>(src + e0 + 4));
    }

    for (; e0 < Emain; e0 += estep) {
        // gathers issue immediately (src prefetched)
        const int s[8] = {sa.x, sa.y, sa.z, sa.w, sb.x, sb.y, sb.z, sb.w};
        uint2 hvr[8];
#pragma unroll
        for (int u = 0; u < 8; u++)
            hvr[u] = *reinterpret_cast<const uint2*>(h + (size_t)s[u] * NF + j0);

        // prefetch next iteration's src while gathers are in flight
        const int e1 = e0 + estep;
        if (e1 < Emain) {
            sa = __ldcs(reinterpret_cast<const int4*>(src + e1));
            sb = __ldcs(reinterpret_cast<const int4*>(src + e1 + 4));
        }

        const int4   da = __ldcs(reinterpret_cast<const int4*>(dst + e0));
        const int4   db = __ldcs(reinterpret_cast<const int4*>(dst + e0 + 4));
        const float4 na = __ldcs(reinterpret_cast<const float4*>(norm + e0));
        const float4 nb = __ldcs(reinterpret_cast<const float4*>(norm + e0 + 4));

        const int   d[8]  = {da.x, da.y, da.z, da.w, db.x, db.y, db.z, db.w};
        const float nr[8] = {na.x, na.y, na.z, na.w, nb.x, nb.y, nb.z, nb.w};

        // two chunks of 4 edges; ef stays at 28 floats
#pragma unroll
        for (int cch = 0; cch < 2; cch++) {
            float ef[28];
#pragma unroll
            for (int q = 0; q < 7; q++)
                *reinterpret_cast<float4*>(&ef[q * 4]) =
                    __ldcs(reinterpret_cast<const float4*>(
                        efeat + (size_t)(e0 + cch * 4) * EFD + q * 4));

#pragma unroll
            for (int uu = 0; uu < 4; uu++) {
                const int u = cch * 4 + uu;
                float v0 = bias[0], v1 = bias[1], v2 = bias[2], v3 = bias[3];
#pragma unroll
                for (int k = 0; k < EFD; k++) {
                    float x = ef[uu * EFD + k];
                    v0 = fmaf(w[0][k], x, v0);
                    v1 = fmaf(w[1][k], x, v1);
                    v2 = fmaf(w[2][k], x, v2);
                    v3 = fmaf(w[3][k], x, v3);
                }
                __half2 p0 = *reinterpret_cast<__half2*>(&hvr[u].x);
                __half2 p1 = *reinterpret_cast<__half2*>(&hvr[u].y);
                float2 f01 = __half22float2(p0);
                float2 f23 = __half22float2(p1);

                v0 = fmaxf(f01.x + v0, 0.f) * nr[u];
                v1 = fmaxf(f01.y + v1, 0.f) * nr[u];
                v2 = fmaxf(f23.x + v2, 0.f) * nr[u];
                v3 = fmaxf(f23.y + v3, 0.f) * nr[u];

                float* p = out + (size_t)d[u] * NF + j0;
                asm volatile("red.global.add.v4.f32 [%0], {%1, %2, %3, %4};"
                             :: "l"(p), "f"(v0), "f"(v1), "f"(v2), "f"(v3)
                             : "memory");
            }
        }
    }

    // tail — warp 0
    if (warp_id == 0) {
        for (int e = Emain; e < E; e++) {
            const int   se = __ldg(src + e);
            const int   de = __ldg(dst + e);
            const float nre = __ldg(norm + e);
            float efs[EFD];
#pragma unroll
            for (int k = 0; k < EFD; k++)
                efs[k] = __ldg(efeat + (size_t)e * EFD + k);
            uint2 hraw = *reinterpret_cast<const uint2*>(h + (size_t)se * NF + j0);
            __half2 p0 = *reinterpret_cast<__half2*>(&hraw.x);
            __half2 p1 = *reinterpret_cast<__half2*>(&hraw.y);
            float2 f01 = __half22float2(p0);
            float2 f23 = __half22float2(p1);
            float v0 = bias[0], v1 = bias[1], v2 = bias[2], v3 = bias[3];
#pragma unroll
            for (int k = 0; k < EFD; k++) {
                v0 = fmaf(w[0][k], efs[k], v0);
                v1 = fmaf(w[1][k], efs[k], v1);
                v2 = fmaf(w[2][k], efs[k], v2);
                v3 = fmaf(w[3][k], efs[k], v3);
            }
            v0 = fmaxf(f01.x + v0, 0.f) * nre;
            v1 = fmaxf(f01.y + v1, 0.f) * nre;
            v2 = fmaxf(f23.x + v2, 0.f) * nre;
            v3 = fmaxf(f23.y + v3, 0.f) * nre;
            float* p = out + (size_t)de * NF + j0;
            asm volatile("red.global.add.v4.f32 [%0], {%1, %2, %3, %4};"
                         :: "l"(p), "f"(v0), "f"(v1), "f"(v2), "f"(v3)
                         : "memory");
        }
    }
}

// ---------------------------------------------------------------------------
// Launch.  Input order: nfeat, efeat, degs, norm, src, dst, W, b, We, be, root
// ---------------------------------------------------------------------------
extern "C" void kernel_launch(void* const* d_in, const int* in_sizes, int n_in,
                              void* d_out, int out_size)
{
    const float* nfeat = (const float*)d_in[0];
    const float* efeat = (const float*)d_in[1];
    const float* degs  = (const float*)d_in[2];
    const float* norm  = (const float*)d_in[3];
    const int*   src   = (const int*)  d_in[4];
    const int*   dst   = (const int*)  d_in[5];
    const float* W     = (const float*)d_in[6];
    const float* b     = (const float*)d_in[7];
    const float* We    = (const float*)d_in[8];
    const float* be    = (const float*)d_in[9];
    const float* root  = (const float*)d_in[10];
    float* out = (float*)d_out;

    const int N = in_sizes[0] / NF;
    const int E = in_sizes[4];

    __half* h;
    cudaGetSymbolAddress((void**)&h, g_h);

    int gridA = (N + BM - 1) / BM;
    gemm_h_kernel<<<gridA, 256>>>(nfeat, W, b, root, degs, h, out, N);

    int gridB = 1480;
    edge_kernel<<<gridB, 256>>>(efeat, norm, src, dst, We, be, h, out, E);
}